// round 13
// baseline (speedup 1.0000x reference)
#include <cuda_runtime.h>

typedef unsigned long long u64;

// ---------------------------------------------------------------------------
// GraphSAGE (LSTM aggregation), 2 layers. N=50000, DEG=8, F_IN=64, HID=LH=128.
// R13 = R7 with KT=64 (2 tiles, 4 barriers) in the recurrent step kernel:
//   P = X @ Wih^T + b       (fp32 SIMT GEMM, once per layer)
//   step t: gates = gather(P, src_t) + H_{t-1} @ Whh^T    (K=128 GEMM)
//   step 0: elementwise from P.
// Micro-kernel: 8m x 8n fma.rn.f32x2, dup-A smem, transposed h/c state.
// ---------------------------------------------------------------------------

namespace cfg {
constexpr int N    = 50000;
constexpr int NP   = 50048;              // padded to 64 multiple
constexpr int DEG  = 8;
constexpr int E    = N * DEG;
constexpr int F1   = 64;
constexpr int HID  = 128;
constexpr int LH   = 128;
constexpr int G4   = 4 * LH;             // 512 gate columns (interleaved u*4+g)
constexpr int TM   = 64;                 // nodes per block
constexpr int TC   = 128;                // gate columns per block
constexpr int NTHR = 128;
constexpr int KT   = 32;                 // K tile (pgemm / out kernels)
constexpr int KT2  = 64;                 // K tile (step kernel)
constexpr int AST2 = 2 * TM + 4;         // dup-A row stride (132 floats)
constexpr int VST  = HID + 4;            // 132
constexpr int MB   = (N + TM - 1) / TM;  // 782
constexpr float EPS = 1e-5f;
}
using namespace cfg;

// ------------------------- device scratch (no allocs) ----------------------
__device__ float g_P[(size_t)NP * G4];    // precomputed input gates (+bias)
__device__ float g_Bx1[F1 * G4];          // Wih interleaved [k][512], col=u*4+g
__device__ float g_Bh1[LH * G4];          // Whh interleaved
__device__ float g_Bx2[HID * G4];
__device__ float g_Bh2[LH * G4];
__device__ float g_bc1[G4];
__device__ float g_bc2[G4];
__device__ float g_L1T[(F1 + LH) * HID];  // lin W transposed [K][HID]
__device__ float g_L2T[(HID + LH) * HID];
__device__ float g_hA[LH * NP];           // h double buffer, TRANSPOSED [u][n]
__device__ float g_hB[LH * NP];
__device__ float g_cS[LH * NP];           // cell state, TRANSPOSED [u][n]
__device__ float g_h1[N * HID];           // layer-1 output (row-major)
__device__ int   g_src[E];                // normalized int32 source indices

// ------------------------- helpers -----------------------------------------
__device__ __forceinline__ float sigf(float x) {
    return __fdividef(1.0f, 1.0f + __expf(-x));
}
__device__ __forceinline__ float tanhfast(float x) {
    return __fdividef(2.0f, 1.0f + __expf(-2.0f * x)) - 1.0f;
}
__device__ __forceinline__ void fma2(u64& d, u64 a, u64 b) {
    asm("fma.rn.f32x2 %0, %1, %2, %0;" : "+l"(d) : "l"(a), "l"(b));
}
__device__ __forceinline__ float2 unpk(u64 v) {
    float2 r;
    asm("mov.b64 {%0, %1}, %2;" : "=f"(r.x), "=f"(r.y) : "l"(v));
    return r;
}

// Normalize edge_index src row to int32, robust to int64-vs-int32 dtype.
__global__ void cvt_src_kernel(const int* __restrict__ raw) {
    bool w64 = true;
#pragma unroll
    for (int i = 0; i < 32; i++) w64 &= (raw[2 * i + 1] == 0);
    for (int idx = blockIdx.x * blockDim.x + threadIdx.x; idx < E;
         idx += gridDim.x * blockDim.x)
        g_src[idx] = w64 ? raw[2 * idx] : raw[idx];
}

// Build interleaved/transposed weights once per call.
__global__ void prep_kernel(const float* __restrict__ W1ih, const float* __restrict__ W1hh,
                            const float* __restrict__ b1,   const float* __restrict__ l1W,
                            const float* __restrict__ W2ih, const float* __restrict__ W2hh,
                            const float* __restrict__ b2,   const float* __restrict__ l2W) {
    const int stride = gridDim.x * blockDim.x;
    const int t0 = blockIdx.x * blockDim.x + threadIdx.x;
    constexpr int K1 = F1 + LH, K2 = HID + LH;
    for (int idx = t0; idx < F1 * G4; idx += stride) {
        int k = idx / G4, cc = idx % G4, u = cc >> 2, g = cc & 3;
        g_Bx1[idx] = W1ih[(g * LH + u) * F1 + k];
    }
    for (int idx = t0; idx < LH * G4; idx += stride) {
        int k = idx / G4, cc = idx % G4, u = cc >> 2, g = cc & 3;
        g_Bh1[idx] = W1hh[(g * LH + u) * LH + k];
    }
    for (int idx = t0; idx < HID * G4; idx += stride) {
        int k = idx / G4, cc = idx % G4, u = cc >> 2, g = cc & 3;
        g_Bx2[idx] = W2ih[(g * LH + u) * HID + k];
    }
    for (int idx = t0; idx < LH * G4; idx += stride) {
        int k = idx / G4, cc = idx % G4, u = cc >> 2, g = cc & 3;
        g_Bh2[idx] = W2hh[(g * LH + u) * LH + k];
    }
    for (int idx = t0; idx < G4; idx += stride) {
        int u = idx >> 2, g = idx & 3;
        g_bc1[idx] = b1[g * LH + u];
        g_bc2[idx] = b2[g * LH + u];
    }
    for (int idx = t0; idx < K1 * HID; idx += stride) {
        int k = idx / HID, cc = idx % HID;
        g_L1T[idx] = l1W[cc * K1 + k];
    }
    for (int idx = t0; idx < K2 * HID; idx += stride) {
        int k = idx / HID, cc = idx % HID;
        g_L2T[idx] = l2W[cc * K2 + k];
    }
}

// ------------------------- P GEMM: P = X @ Wih^T + b -------------------------
template <int F>
__global__ void __launch_bounds__(NTHR, 3)
pgemm_kernel(const float* __restrict__ xin, const float* __restrict__ Bx,
             const float* __restrict__ bx) {
    constexpr int NT = F / KT;
    __shared__ float sA[KT][AST2];
    __shared__ float sB[KT][TC];

    const int tid  = threadIdx.x;
    const int m0   = blockIdx.x * TM;
    const int c0   = blockIdx.y * TC;
    const int nIdx = tid & 15;
    const int mIdx = tid >> 4;

    u64 acc[8][4];
    {
        ulonglong2 b0 = *reinterpret_cast<const ulonglong2*>(bx + c0 + nIdx * 4);
        ulonglong2 b1 = *reinterpret_cast<const ulonglong2*>(bx + c0 + 64 + nIdx * 4);
        u64 bj[4] = {b0.x, b0.y, b1.x, b1.y};
#pragma unroll
        for (int i = 0; i < 8; i++)
#pragma unroll
            for (int j = 0; j < 4; j++) acc[i][j] = bj[j];
    }

#pragma unroll 1
    for (int kt = 0; kt < NT; kt++) {
        const int k0 = kt * KT;
        __syncthreads();
#pragma unroll
        for (int it = 0; it < 4; it++) {
            int idx = tid + it * NTHR;
            int m = idx & 63, kq = idx >> 6;
            int row = m0 + m;
            row = row < N ? row : N - 1;
            float4 v = *reinterpret_cast<const float4*>(xin + (size_t)row * F + k0 + kq * 4);
            float* d = &sA[kq * 4][2 * m];
            *reinterpret_cast<float2*>(d)            = make_float2(v.x, v.x);
            *reinterpret_cast<float2*>(d + AST2)     = make_float2(v.y, v.y);
            *reinterpret_cast<float2*>(d + 2 * AST2) = make_float2(v.z, v.z);
            *reinterpret_cast<float2*>(d + 3 * AST2) = make_float2(v.w, v.w);
        }
#pragma unroll
        for (int it = 0; it < 8; it++) {
            int idx = tid + it * NTHR;
            int kk = idx >> 5, q = idx & 31;
            *reinterpret_cast<float4*>(&sB[kk][4 * q]) =
                *reinterpret_cast<const float4*>(Bx + (size_t)(k0 + kk) * G4 + c0 + 4 * q);
        }
        __syncthreads();

#pragma unroll 4
        for (int kk = 0; kk < KT; kk++) {
            const float* ra = &sA[kk][mIdx * 16];
            ulonglong2 a0 = *reinterpret_cast<const ulonglong2*>(ra);
            ulonglong2 a1 = *reinterpret_cast<const ulonglong2*>(ra + 4);
            ulonglong2 a2 = *reinterpret_cast<const ulonglong2*>(ra + 8);
            ulonglong2 a3 = *reinterpret_cast<const ulonglong2*>(ra + 12);
            ulonglong2 b01 = *reinterpret_cast<const ulonglong2*>(&sB[kk][nIdx * 4]);
            ulonglong2 b23 = *reinterpret_cast<const ulonglong2*>(&sB[kk][64 + nIdx * 4]);
            u64 a[8] = {a0.x, a0.y, a1.x, a1.y, a2.x, a2.y, a3.x, a3.y};
            u64 b[4] = {b01.x, b01.y, b23.x, b23.y};
#pragma unroll
            for (int i = 0; i < 8; i++)
#pragma unroll
                for (int j = 0; j < 4; j++) fma2(acc[i][j], a[i], b[j]);
        }
    }

    const int nb = m0 + mIdx * 8;
#pragma unroll
    for (int i = 0; i < 8; i++) {
        float* pr = g_P + (size_t)(nb + i) * G4 + c0 + nIdx * 4;
        ulonglong2 v0; v0.x = acc[i][0]; v0.y = acc[i][1];
        ulonglong2 v1; v1.x = acc[i][2]; v1.y = acc[i][3];
        *reinterpret_cast<ulonglong2*>(pr)      = v0;
        *reinterpret_cast<ulonglong2*>(pr + 64) = v1;
    }
}

// ------------------------- step 0: gates = gather(P) -------------------------
__global__ void __launch_bounds__(256)
step0_kernel(float* __restrict__ hT, float* __restrict__ cT) {
    int gid  = blockIdx.x * blockDim.x + threadIdx.x;
    int w    = gid >> 5, lane = gid & 31;
    int u    = w & 127;
    int n    = ((w >> 7) << 5) + lane;     // 0..NP-1
    int nn   = n < N ? n : N - 1;
    int src  = g_src[nn * DEG + 0];
    float4 g = *reinterpret_cast<const float4*>(g_P + (size_t)src * G4 + u * 4);
    float cn = sigf(g.x) * tanhfast(g.z);
    float hn = sigf(g.w) * tanhfast(cn);
    cT[(size_t)u * NP + n] = cn;
    hT[(size_t)u * NP + n] = hn;
}

// ------------------------- LSTM step (t >= 1), KT2=64 ------------------------
// gates[TM x TC] = gather(P, src_t) + h_in[TM x 128] @ Bh_slice[128 x TC]
__global__ void __launch_bounds__(NTHR, 3)
lstm_step_kernel(int t, const float* __restrict__ Bh,
                 const float* __restrict__ hinT, float* __restrict__ houtT,
                 float* __restrict__ cstT) {
    constexpr int NT = LH / KT2;      // 2
    extern __shared__ float smem[];
    float* const sA = smem;                   // [KT2][AST2] dup-A
    float* const sB = smem + KT2 * AST2;      // [KT2][TC]
    __shared__ int sSrc[TM];

    const int tid  = threadIdx.x;
    const int m0   = blockIdx.x * TM;
    const int c0   = blockIdx.y * TC;
    const int nIdx = tid & 15;
    const int mIdx = tid >> 4;

    if (tid < TM) {
        int n = m0 + tid;
        sSrc[tid] = (n < N) ? g_src[n * DEG + t] : 0;
    }
    __syncthreads();

    // acc init: gathered P rows (bias included)
    u64 acc[8][4];
#pragma unroll
    for (int i = 0; i < 8; i++) {
        const float* pr = g_P + (size_t)sSrc[mIdx * 8 + i] * G4 + c0 + nIdx * 4;
        ulonglong2 a = *reinterpret_cast<const ulonglong2*>(pr);
        ulonglong2 b = *reinterpret_cast<const ulonglong2*>(pr + 64);
        acc[i][0] = a.x; acc[i][1] = a.y; acc[i][2] = b.x; acc[i][3] = b.y;
    }

#pragma unroll 1
    for (int kt = 0; kt < NT; kt++) {
        const int k0 = kt * KT2;
        __syncthreads();
        // A: transposed-h rows, contiguous copy, conflict-free dup-store
#pragma unroll
        for (int it = 0; it < 16; it++) {
            int idx = tid + it * NTHR;          // 0..2047
            int kk = idx >> 5, p = idx & 31;
            float2 v = *reinterpret_cast<const float2*>(
                hinT + (size_t)(k0 + kk) * NP + m0 + 2 * p);
            *reinterpret_cast<float4*>(sA + (size_t)kk * AST2 + 4 * p) =
                make_float4(v.x, v.x, v.y, v.y);
        }
        // B slice
#pragma unroll
        for (int it = 0; it < 16; it++) {
            int idx = tid + it * NTHR;          // 0..2047
            int kk = idx >> 5, q = idx & 31;
            *reinterpret_cast<float4*>(sB + (size_t)kk * TC + 4 * q) =
                *reinterpret_cast<const float4*>(Bh + (size_t)(k0 + kk) * G4 + c0 + 4 * q);
        }
        __syncthreads();

#pragma unroll 4
        for (int kk = 0; kk < KT2; kk++) {
            const float* ra = sA + (size_t)kk * AST2 + mIdx * 16;
            const float* rb = sB + (size_t)kk * TC;
            ulonglong2 a0 = *reinterpret_cast<const ulonglong2*>(ra);
            ulonglong2 a1 = *reinterpret_cast<const ulonglong2*>(ra + 4);
            ulonglong2 a2 = *reinterpret_cast<const ulonglong2*>(ra + 8);
            ulonglong2 a3 = *reinterpret_cast<const ulonglong2*>(ra + 12);
            ulonglong2 b01 = *reinterpret_cast<const ulonglong2*>(rb + nIdx * 4);
            ulonglong2 b23 = *reinterpret_cast<const ulonglong2*>(rb + 64 + nIdx * 4);
            u64 a[8] = {a0.x, a0.y, a1.x, a1.y, a2.x, a2.y, a3.x, a3.y};
            u64 b[4] = {b01.x, b01.y, b23.x, b23.y};
#pragma unroll
            for (int i = 0; i < 8; i++)
#pragma unroll
                for (int j = 0; j < 4; j++) fma2(acc[i][j], a[i], b[j]);
        }
    }

    // epilogue: thread owns units u0 = c0/4 + nIdx and u0 + 16, 8 consecutive n
    const int u0 = (c0 >> 2) + nIdx;
    const int u1 = u0 + 16;
    const int nb = m0 + mIdx * 8;
    float h0[8], h1v[8], c0v[8], c1v[8], co0[8], co1[8];
#pragma unroll
    for (int q = 0; q < 2; q++) {
        float4 a = *reinterpret_cast<const float4*>(cstT + (size_t)u0 * NP + nb + 4 * q);
        float4 b = *reinterpret_cast<const float4*>(cstT + (size_t)u1 * NP + nb + 4 * q);
        co0[4 * q] = a.x; co0[4 * q + 1] = a.y; co0[4 * q + 2] = a.z; co0[4 * q + 3] = a.w;
        co1[4 * q] = b.x; co1[4 * q + 1] = b.y; co1[4 * q + 2] = b.z; co1[4 * q + 3] = b.w;
    }
#pragma unroll
    for (int i = 0; i < 8; i++) {
        float2 if0 = unpk(acc[i][0]);   // (i, f) of u0
        float2 go0 = unpk(acc[i][1]);   // (g, o) of u0
        float2 if1 = unpk(acc[i][2]);
        float2 go1 = unpk(acc[i][3]);
        {
            float cn = sigf(if0.y) * co0[i] + sigf(if0.x) * tanhfast(go0.x);
            c0v[i] = cn;
            h0[i]  = sigf(go0.y) * tanhfast(cn);
        }
        {
            float cn = sigf(if1.y) * co1[i] + sigf(if1.x) * tanhfast(go1.x);
            c1v[i] = cn;
            h1v[i] = sigf(go1.y) * tanhfast(cn);
        }
    }
#pragma unroll
    for (int q = 0; q < 2; q++) {
        *reinterpret_cast<float4*>(cstT + (size_t)u0 * NP + nb + 4 * q) =
            make_float4(c0v[4 * q], c0v[4 * q + 1], c0v[4 * q + 2], c0v[4 * q + 3]);
        *reinterpret_cast<float4*>(cstT + (size_t)u1 * NP + nb + 4 * q) =
            make_float4(c1v[4 * q], c1v[4 * q + 1], c1v[4 * q + 2], c1v[4 * q + 3]);
        *reinterpret_cast<float4*>(houtT + (size_t)u0 * NP + nb + 4 * q) =
            make_float4(h0[4 * q], h0[4 * q + 1], h0[4 * q + 2], h0[4 * q + 3]);
        *reinterpret_cast<float4*>(houtT + (size_t)u1 * NP + nb + 4 * q) =
            make_float4(h1v[4 * q], h1v[4 * q + 1], h1v[4 * q + 2], h1v[4 * q + 3]);
    }
}

// ------------------------- linear + ReLU + LayerNorm ------------------------
template <int F, bool RELU_OUT>
__global__ void __launch_bounds__(NTHR, 3)
out_kernel(const float* __restrict__ xin, const float* __restrict__ hfinT,
           const float* __restrict__ LT, const float* __restrict__ lb,
           const float* __restrict__ gma, const float* __restrict__ bta,
           float* __restrict__ out) {
    constexpr int K  = F + LH;
    constexpr int NT = K / KT;
    __shared__ float pool[TM * VST];
    float* sAf = pool;
    float* sBf = pool + KT * AST2;
    float* sV  = pool;
    __shared__ float sMu[TM], sR[TM];

    const int tid  = threadIdx.x;
    const int m0   = blockIdx.x * TM;
    const int nIdx = tid & 15;
    const int mIdx = tid >> 4;

    u64 acc[8][4];
    {
        ulonglong2 b0 = *reinterpret_cast<const ulonglong2*>(lb + nIdx * 4);
        ulonglong2 b1 = *reinterpret_cast<const ulonglong2*>(lb + 64 + nIdx * 4);
        u64 bj[4] = {b0.x, b0.y, b1.x, b1.y};
#pragma unroll
        for (int i = 0; i < 8; i++)
#pragma unroll
            for (int j = 0; j < 4; j++) acc[i][j] = bj[j];
    }

#pragma unroll 1
    for (int kt = 0; kt < NT; kt++) {
        const int k0 = kt * KT;
        __syncthreads();
        if (k0 < F) {
#pragma unroll
            for (int it = 0; it < 4; it++) {
                int idx = tid + it * NTHR;
                int m = idx & 63, kq = idx >> 6;
                int row = m0 + m;
                row = row < N ? row : N - 1;
                float4 v = *reinterpret_cast<const float4*>(xin + (size_t)row * F + k0 + kq * 4);
                float* base = sAf + (size_t)(kq * 4) * AST2 + 2 * m;
                *reinterpret_cast<float2*>(base)            = make_float2(v.x, v.x);
                *reinterpret_cast<float2*>(base + AST2)     = make_float2(v.y, v.y);
                *reinterpret_cast<float2*>(base + 2 * AST2) = make_float2(v.z, v.z);
                *reinterpret_cast<float2*>(base + 3 * AST2) = make_float2(v.w, v.w);
            }
        } else {
#pragma unroll
            for (int it = 0; it < 8; it++) {
                int idx = tid + it * NTHR;
                int kk = idx >> 5, p = idx & 31;
                float2 v = *reinterpret_cast<const float2*>(
                    hfinT + (size_t)(k0 - F + kk) * NP + m0 + 2 * p);
                *reinterpret_cast<float4*>(sAf + (size_t)kk * AST2 + 4 * p) =
                    make_float4(v.x, v.x, v.y, v.y);
            }
        }
#pragma unroll
        for (int it = 0; it < 8; it++) {
            int idx = tid + it * NTHR;
            int kk = idx >> 5, q = idx & 31;
            *reinterpret_cast<float4*>(sBf + (size_t)kk * HID + 4 * q) =
                *reinterpret_cast<const float4*>(LT + (size_t)(k0 + kk) * HID + 4 * q);
        }
        __syncthreads();

#pragma unroll 4
        for (int kk = 0; kk < KT; kk++) {
            const float* ra = sAf + (size_t)kk * AST2 + mIdx * 16;
            const float* rb = sBf + (size_t)kk * HID;
            ulonglong2 a0 = *reinterpret_cast<const ulonglong2*>(ra);
            ulonglong2 a1 = *reinterpret_cast<const ulonglong2*>(ra + 4);
            ulonglong2 a2 = *reinterpret_cast<const ulonglong2*>(ra + 8);
            ulonglong2 a3 = *reinterpret_cast<const ulonglong2*>(ra + 12);
            ulonglong2 b01 = *reinterpret_cast<const ulonglong2*>(rb + nIdx * 4);
            ulonglong2 b23 = *reinterpret_cast<const ulonglong2*>(rb + 64 + nIdx * 4);
            u64 a[8] = {a0.x, a0.y, a1.x, a1.y, a2.x, a2.y, a3.x, a3.y};
            u64 b[4] = {b01.x, b01.y, b23.x, b23.y};
#pragma unroll
            for (int i = 0; i < 8; i++)
#pragma unroll
                for (int j = 0; j < 4; j++) fma2(acc[i][j], a[i], b[j]);
        }
    }
    __syncthreads();

#pragma unroll
    for (int i = 0; i < 8; i++) {
        float* row = sV + (size_t)(mIdx * 8 + i) * VST;
        float2 p0 = unpk(acc[i][0]), p1 = unpk(acc[i][1]);
        float2 p2 = unpk(acc[i][2]), p3 = unpk(acc[i][3]);
        *reinterpret_cast<float4*>(row + nIdx * 4) =
            make_float4(fmaxf(p0.x, 0.f), fmaxf(p0.y, 0.f), fmaxf(p1.x, 0.f), fmaxf(p1.y, 0.f));
        *reinterpret_cast<float4*>(row + 64 + nIdx * 4) =
            make_float4(fmaxf(p2.x, 0.f), fmaxf(p2.y, 0.f), fmaxf(p3.x, 0.f), fmaxf(p3.y, 0.f));
    }
    __syncthreads();

    if (tid < TM) {
        float s = 0.0f, s2 = 0.0f;
        for (int cidx = 0; cidx < HID; cidx++) {
            float v = sV[(size_t)tid * VST + cidx];
            s += v; s2 += v * v;
        }
        float mu  = s * (1.0f / HID);
        float var = s2 * (1.0f / HID) - mu * mu;
        sMu[tid] = mu;
        sR[tid]  = rsqrtf(var + EPS);
    }
    __syncthreads();

    for (int idx = tid; idx < TM * HID; idx += NTHR) {
        int m = idx >> 7, cc = idx & 127;
        int n = m0 + m;
        if (n < N) {
            float v = (sV[(size_t)m * VST + cc] - sMu[m]) * sR[m] * gma[cc] + bta[cc];
            out[(size_t)n * HID + cc] = RELU_OUT ? fmaxf(v, 0.0f) : v;
        }
    }
}

// ------------------------- launch --------------------------------------------
extern "C" void kernel_launch(void* const* d_in, const int* in_sizes, int n_in,
                              void* d_out, int out_size) {
    const float* x    = (const float*)d_in[0];
    const int*   eraw = (const int*)d_in[1];
    const float* W1ih = (const float*)d_in[2];
    const float* W1hh = (const float*)d_in[3];
    const float* b1   = (const float*)d_in[4];
    const float* l1W  = (const float*)d_in[5];
    const float* l1b  = (const float*)d_in[6];
    const float* g1   = (const float*)d_in[7];
    const float* be1  = (const float*)d_in[8];
    const float* W2ih = (const float*)d_in[9];
    const float* W2hh = (const float*)d_in[10];
    const float* b2   = (const float*)d_in[11];
    const float* l2W  = (const float*)d_in[12];
    const float* l2b  = (const float*)d_in[13];
    const float* g2   = (const float*)d_in[14];
    const float* be2  = (const float*)d_in[15];

    float *pBx1, *pBh1, *pBx2, *pBh2, *pbc1, *pbc2, *pL1, *pL2;
    float *phA, *phB, *pc, *ph1;
    cudaGetSymbolAddress((void**)&pBx1, g_Bx1);
    cudaGetSymbolAddress((void**)&pBh1, g_Bh1);
    cudaGetSymbolAddress((void**)&pBx2, g_Bx2);
    cudaGetSymbolAddress((void**)&pBh2, g_Bh2);
    cudaGetSymbolAddress((void**)&pbc1, g_bc1);
    cudaGetSymbolAddress((void**)&pbc2, g_bc2);
    cudaGetSymbolAddress((void**)&pL1, g_L1T);
    cudaGetSymbolAddress((void**)&pL2, g_L2T);
    cudaGetSymbolAddress((void**)&phA, g_hA);
    cudaGetSymbolAddress((void**)&phB, g_hB);
    cudaGetSymbolAddress((void**)&pc, g_cS);
    cudaGetSymbolAddress((void**)&ph1, g_h1);

    const int s_step = (KT2 * AST2 + KT2 * TC) * 4;   // 66,560 B
    cudaFuncSetAttribute((const void*)lstm_step_kernel,
                         cudaFuncAttributeMaxDynamicSharedMemorySize, s_step);

    cvt_src_kernel<<<(E + 1023) / 1024, 1024>>>(eraw);
    prep_kernel<<<256, 256>>>(W1ih, W1hh, b1, l1W, W2ih, W2hh, b2, l2W);

    const dim3 pgrid(MB, G4 / TC);          // 782 x 4
    const int  s0blocks = (128 * NP) / 256; // 25024

    // ---------------- layer 1 ----------------
    pgemm_kernel<F1><<<pgrid, NTHR>>>(x, pBx1, pbc1);
    step0_kernel<<<s0blocks, 256>>>(phA, pc);
    for (int t = 1; t < DEG; t++) {
        float* hw = (t & 1) ? phB : phA;
        float* hr = (t & 1) ? phA : phB;
        lstm_step_kernel<<<pgrid, NTHR, s_step>>>(t, pBh1, hr, hw, pc);
    }
    // t = 7 (odd) -> final h in phB
    out_kernel<F1, true><<<MB, NTHR>>>(x, phB, pL1, l1b, g1, be1, ph1);

    // ---------------- layer 2 ----------------
    pgemm_kernel<HID><<<pgrid, NTHR>>>(ph1, pBx2, pbc2);
    step0_kernel<<<s0blocks, 256>>>(phA, pc);
    for (int t = 1; t < DEG; t++) {
        float* hw = (t & 1) ? phB : phA;
        float* hr = (t & 1) ? phA : phB;
        lstm_step_kernel<<<pgrid, NTHR, s_step>>>(t, pBh2, hr, hw, pc);
    }
    out_kernel<HID, false><<<MB, NTHR>>>(ph1, phB, pL2, l2b, g2, be2, (float*)d_out);
}

// round 14
// speedup vs baseline: 1.0686x; 1.0686x over previous
#include <cuda_runtime.h>

typedef unsigned long long u64;

// ---------------------------------------------------------------------------
// GraphSAGE (LSTM aggregation), 2 layers. N=50000, DEG=8, F_IN=64, HID=LH=128.
// R14 = R7 with deletions in the step kernel only:
//   - per-thread direct src reads (no sSrc smem, -2 barriers)
//   - P-gather LDGs issued first; tile-0 loads peeled (kt=0 barrier removed)
//   P = X @ Wih^T + b       (fp32 SIMT GEMM, once per layer)
//   step t: gates = gather(P, src_t) + H_{t-1} @ Whh^T    (K=128 GEMM)
//   step 0: elementwise from P.
// Micro-kernel: 8m x 8n fma.rn.f32x2, dup-A smem, transposed h/c state.
// ---------------------------------------------------------------------------

namespace cfg {
constexpr int N    = 50000;
constexpr int NP   = 50048;              // padded to 64 multiple
constexpr int DEG  = 8;
constexpr int E    = N * DEG;
constexpr int F1   = 64;
constexpr int HID  = 128;
constexpr int LH   = 128;
constexpr int G4   = 4 * LH;             // 512 gate columns (interleaved u*4+g)
constexpr int TM   = 64;                 // nodes per block
constexpr int TC   = 128;                // gate columns per block
constexpr int NTHR = 128;
constexpr int KT   = 32;                 // K tile
constexpr int AST2 = 2 * TM + 4;         // dup-A row stride (132 floats)
constexpr int VST  = HID + 4;            // 132
constexpr int MB   = (N + TM - 1) / TM;  // 782
constexpr float EPS = 1e-5f;
}
using namespace cfg;

// ------------------------- device scratch (no allocs) ----------------------
__device__ float g_P[(size_t)NP * G4];    // precomputed input gates (+bias)
__device__ float g_Bx1[F1 * G4];          // Wih interleaved [k][512], col=u*4+g
__device__ float g_Bh1[LH * G4];          // Whh interleaved
__device__ float g_Bx2[HID * G4];
__device__ float g_Bh2[LH * G4];
__device__ float g_bc1[G4];
__device__ float g_bc2[G4];
__device__ float g_L1T[(F1 + LH) * HID];  // lin W transposed [K][HID]
__device__ float g_L2T[(HID + LH) * HID];
__device__ float g_hA[LH * NP];           // h double buffer, TRANSPOSED [u][n]
__device__ float g_hB[LH * NP];
__device__ float g_cS[LH * NP];           // cell state, TRANSPOSED [u][n]
__device__ float g_h1[N * HID];           // layer-1 output (row-major)
__device__ int   g_src[E];                // normalized int32 source indices

// ------------------------- helpers -----------------------------------------
__device__ __forceinline__ float sigf(float x) {
    return __fdividef(1.0f, 1.0f + __expf(-x));
}
__device__ __forceinline__ float tanhfast(float x) {
    return __fdividef(2.0f, 1.0f + __expf(-2.0f * x)) - 1.0f;
}
__device__ __forceinline__ void fma2(u64& d, u64 a, u64 b) {
    asm("fma.rn.f32x2 %0, %1, %2, %0;" : "+l"(d) : "l"(a), "l"(b));
}
__device__ __forceinline__ float2 unpk(u64 v) {
    float2 r;
    asm("mov.b64 {%0, %1}, %2;" : "=f"(r.x), "=f"(r.y) : "l"(v));
    return r;
}

// Normalize edge_index src row to int32, robust to int64-vs-int32 dtype.
__global__ void cvt_src_kernel(const int* __restrict__ raw) {
    bool w64 = true;
#pragma unroll
    for (int i = 0; i < 32; i++) w64 &= (raw[2 * i + 1] == 0);
    for (int idx = blockIdx.x * blockDim.x + threadIdx.x; idx < E;
         idx += gridDim.x * blockDim.x)
        g_src[idx] = w64 ? raw[2 * idx] : raw[idx];
}

// Build interleaved/transposed weights once per call.
__global__ void prep_kernel(const float* __restrict__ W1ih, const float* __restrict__ W1hh,
                            const float* __restrict__ b1,   const float* __restrict__ l1W,
                            const float* __restrict__ W2ih, const float* __restrict__ W2hh,
                            const float* __restrict__ b2,   const float* __restrict__ l2W) {
    const int stride = gridDim.x * blockDim.x;
    const int t0 = blockIdx.x * blockDim.x + threadIdx.x;
    constexpr int K1 = F1 + LH, K2 = HID + LH;
    for (int idx = t0; idx < F1 * G4; idx += stride) {
        int k = idx / G4, cc = idx % G4, u = cc >> 2, g = cc & 3;
        g_Bx1[idx] = W1ih[(g * LH + u) * F1 + k];
    }
    for (int idx = t0; idx < LH * G4; idx += stride) {
        int k = idx / G4, cc = idx % G4, u = cc >> 2, g = cc & 3;
        g_Bh1[idx] = W1hh[(g * LH + u) * LH + k];
    }
    for (int idx = t0; idx < HID * G4; idx += stride) {
        int k = idx / G4, cc = idx % G4, u = cc >> 2, g = cc & 3;
        g_Bx2[idx] = W2ih[(g * LH + u) * HID + k];
    }
    for (int idx = t0; idx < LH * G4; idx += stride) {
        int k = idx / G4, cc = idx % G4, u = cc >> 2, g = cc & 3;
        g_Bh2[idx] = W2hh[(g * LH + u) * LH + k];
    }
    for (int idx = t0; idx < G4; idx += stride) {
        int u = idx >> 2, g = idx & 3;
        g_bc1[idx] = b1[g * LH + u];
        g_bc2[idx] = b2[g * LH + u];
    }
    for (int idx = t0; idx < K1 * HID; idx += stride) {
        int k = idx / HID, cc = idx % HID;
        g_L1T[idx] = l1W[cc * K1 + k];
    }
    for (int idx = t0; idx < K2 * HID; idx += stride) {
        int k = idx / HID, cc = idx % HID;
        g_L2T[idx] = l2W[cc * K2 + k];
    }
}

// ------------------------- P GEMM: P = X @ Wih^T + b -------------------------
template <int F>
__global__ void __launch_bounds__(NTHR, 3)
pgemm_kernel(const float* __restrict__ xin, const float* __restrict__ Bx,
             const float* __restrict__ bx) {
    constexpr int NT = F / KT;
    __shared__ float sA[KT][AST2];
    __shared__ float sB[KT][TC];

    const int tid  = threadIdx.x;
    const int m0   = blockIdx.x * TM;
    const int c0   = blockIdx.y * TC;
    const int nIdx = tid & 15;
    const int mIdx = tid >> 4;

    u64 acc[8][4];
    {
        ulonglong2 b0 = *reinterpret_cast<const ulonglong2*>(bx + c0 + nIdx * 4);
        ulonglong2 b1 = *reinterpret_cast<const ulonglong2*>(bx + c0 + 64 + nIdx * 4);
        u64 bj[4] = {b0.x, b0.y, b1.x, b1.y};
#pragma unroll
        for (int i = 0; i < 8; i++)
#pragma unroll
            for (int j = 0; j < 4; j++) acc[i][j] = bj[j];
    }

#pragma unroll 1
    for (int kt = 0; kt < NT; kt++) {
        const int k0 = kt * KT;
        __syncthreads();
#pragma unroll
        for (int it = 0; it < 4; it++) {
            int idx = tid + it * NTHR;
            int m = idx & 63, kq = idx >> 6;
            int row = m0 + m;
            row = row < N ? row : N - 1;
            float4 v = *reinterpret_cast<const float4*>(xin + (size_t)row * F + k0 + kq * 4);
            float* d = &sA[kq * 4][2 * m];
            *reinterpret_cast<float2*>(d)            = make_float2(v.x, v.x);
            *reinterpret_cast<float2*>(d + AST2)     = make_float2(v.y, v.y);
            *reinterpret_cast<float2*>(d + 2 * AST2) = make_float2(v.z, v.z);
            *reinterpret_cast<float2*>(d + 3 * AST2) = make_float2(v.w, v.w);
        }
#pragma unroll
        for (int it = 0; it < 8; it++) {
            int idx = tid + it * NTHR;
            int kk = idx >> 5, q = idx & 31;
            *reinterpret_cast<float4*>(&sB[kk][4 * q]) =
                *reinterpret_cast<const float4*>(Bx + (size_t)(k0 + kk) * G4 + c0 + 4 * q);
        }
        __syncthreads();

#pragma unroll 4
        for (int kk = 0; kk < KT; kk++) {
            const float* ra = &sA[kk][mIdx * 16];
            ulonglong2 a0 = *reinterpret_cast<const ulonglong2*>(ra);
            ulonglong2 a1 = *reinterpret_cast<const ulonglong2*>(ra + 4);
            ulonglong2 a2 = *reinterpret_cast<const ulonglong2*>(ra + 8);
            ulonglong2 a3 = *reinterpret_cast<const ulonglong2*>(ra + 12);
            ulonglong2 b01 = *reinterpret_cast<const ulonglong2*>(&sB[kk][nIdx * 4]);
            ulonglong2 b23 = *reinterpret_cast<const ulonglong2*>(&sB[kk][64 + nIdx * 4]);
            u64 a[8] = {a0.x, a0.y, a1.x, a1.y, a2.x, a2.y, a3.x, a3.y};
            u64 b[4] = {b01.x, b01.y, b23.x, b23.y};
#pragma unroll
            for (int i = 0; i < 8; i++)
#pragma unroll
                for (int j = 0; j < 4; j++) fma2(acc[i][j], a[i], b[j]);
        }
    }

    const int nb = m0 + mIdx * 8;
#pragma unroll
    for (int i = 0; i < 8; i++) {
        float* pr = g_P + (size_t)(nb + i) * G4 + c0 + nIdx * 4;
        ulonglong2 v0; v0.x = acc[i][0]; v0.y = acc[i][1];
        ulonglong2 v1; v1.x = acc[i][2]; v1.y = acc[i][3];
        *reinterpret_cast<ulonglong2*>(pr)      = v0;
        *reinterpret_cast<ulonglong2*>(pr + 64) = v1;
    }
}

// ------------------------- step 0: gates = gather(P) -------------------------
__global__ void __launch_bounds__(256)
step0_kernel(float* __restrict__ hT, float* __restrict__ cT) {
    int gid  = blockIdx.x * blockDim.x + threadIdx.x;
    int w    = gid >> 5, lane = gid & 31;
    int u    = w & 127;
    int n    = ((w >> 7) << 5) + lane;     // 0..NP-1
    int nn   = n < N ? n : N - 1;
    int src  = g_src[nn * DEG + 0];
    float4 g = *reinterpret_cast<const float4*>(g_P + (size_t)src * G4 + u * 4);
    float cn = sigf(g.x) * tanhfast(g.z);
    float hn = sigf(g.w) * tanhfast(cn);
    cT[(size_t)u * NP + n] = cn;
    hT[(size_t)u * NP + n] = hn;
}

// ------------------------- LSTM step (t >= 1) --------------------------------
// gates[TM x TC] = gather(P, src_t) + h_in[TM x 128] @ Bh_slice[128 x TC]
// No sSrc staging; P-gather LDGs issue first; tile-0 loads peeled.
__global__ void __launch_bounds__(NTHR, 3)
lstm_step_kernel(int t, const float* __restrict__ Bh,
                 const float* __restrict__ hinT, float* __restrict__ houtT,
                 float* __restrict__ cstT) {
    constexpr int NT = LH / KT;  // 4
    __shared__ float sA[KT][AST2];
    __shared__ float sB[KT][TC];

    const int tid  = threadIdx.x;
    const int m0   = blockIdx.x * TM;
    const int c0   = blockIdx.y * TC;
    const int nIdx = tid & 15;
    const int mIdx = tid >> 4;

    // acc init: per-thread src reads + gathered P rows (bias included).
    // Threads sharing mIdx read identical addresses -> broadcast wavefronts.
    u64 acc[8][4];
#pragma unroll
    for (int i = 0; i < 8; i++) {
        int n = m0 + mIdx * 8 + i;
        int nn = n < N ? n : N - 1;
        int s = g_src[nn * DEG + t];
        const float* pr = g_P + (size_t)s * G4 + c0 + nIdx * 4;
        ulonglong2 a = *reinterpret_cast<const ulonglong2*>(pr);
        ulonglong2 b = *reinterpret_cast<const ulonglong2*>(pr + 64);
        acc[i][0] = a.x; acc[i][1] = a.y; acc[i][2] = b.x; acc[i][3] = b.y;
    }

    // tile loader: A (transposed-h rows, dup-store) + B (Whh slice)
    auto load_tile = [&](int k0) {
#pragma unroll
        for (int it = 0; it < 8; it++) {
            int idx = tid + it * NTHR;          // 0..1023
            int kk = idx >> 5, p = idx & 31;
            float2 v = *reinterpret_cast<const float2*>(
                hinT + (size_t)(k0 + kk) * NP + m0 + 2 * p);
            *reinterpret_cast<float4*>(&sA[kk][4 * p]) =
                make_float4(v.x, v.x, v.y, v.y);
        }
#pragma unroll
        for (int it = 0; it < 8; it++) {
            int idx = tid + it * NTHR;
            int kk = idx >> 5, q = idx & 31;
            *reinterpret_cast<float4*>(&sB[kk][4 * q]) =
                *reinterpret_cast<const float4*>(Bh + (size_t)(k0 + kk) * G4 + c0 + 4 * q);
        }
    };

    load_tile(0);      // peeled tile-0 loads (overlap the P-gather latency)

#pragma unroll 1
    for (int kt = 0; kt < NT; kt++) {
        __syncthreads();                        // tile kt ready

#pragma unroll 4
        for (int kk = 0; kk < KT; kk++) {
            const float* ra = &sA[kk][mIdx * 16];
            ulonglong2 a0 = *reinterpret_cast<const ulonglong2*>(ra);
            ulonglong2 a1 = *reinterpret_cast<const ulonglong2*>(ra + 4);
            ulonglong2 a2 = *reinterpret_cast<const ulonglong2*>(ra + 8);
            ulonglong2 a3 = *reinterpret_cast<const ulonglong2*>(ra + 12);
            ulonglong2 b01 = *reinterpret_cast<const ulonglong2*>(&sB[kk][nIdx * 4]);
            ulonglong2 b23 = *reinterpret_cast<const ulonglong2*>(&sB[kk][64 + nIdx * 4]);
            u64 a[8] = {a0.x, a0.y, a1.x, a1.y, a2.x, a2.y, a3.x, a3.y};
            u64 b[4] = {b01.x, b01.y, b23.x, b23.y};
#pragma unroll
            for (int i = 0; i < 8; i++)
#pragma unroll
                for (int j = 0; j < 4; j++) fma2(acc[i][j], a[i], b[j]);
        }

        if (kt + 1 < NT) {
            __syncthreads();                    // compute done; smem reusable
            load_tile((kt + 1) * KT);
        }
    }

    // epilogue: thread owns units u0 = c0/4 + nIdx and u0 + 16, 8 consecutive n
    const int u0 = (c0 >> 2) + nIdx;
    const int u1 = u0 + 16;
    const int nb = m0 + mIdx * 8;
    float h0[8], h1v[8], c0v[8], c1v[8], co0[8], co1[8];
#pragma unroll
    for (int q = 0; q < 2; q++) {
        float4 a = *reinterpret_cast<const float4*>(cstT + (size_t)u0 * NP + nb + 4 * q);
        float4 b = *reinterpret_cast<const float4*>(cstT + (size_t)u1 * NP + nb + 4 * q);
        co0[4 * q] = a.x; co0[4 * q + 1] = a.y; co0[4 * q + 2] = a.z; co0[4 * q + 3] = a.w;
        co1[4 * q] = b.x; co1[4 * q + 1] = b.y; co1[4 * q + 2] = b.z; co1[4 * q + 3] = b.w;
    }
#pragma unroll
    for (int i = 0; i < 8; i++) {
        float2 if0 = unpk(acc[i][0]);   // (i, f) of u0
        float2 go0 = unpk(acc[i][1]);   // (g, o) of u0
        float2 if1 = unpk(acc[i][2]);
        float2 go1 = unpk(acc[i][3]);
        {
            float cn = sigf(if0.y) * co0[i] + sigf(if0.x) * tanhfast(go0.x);
            c0v[i] = cn;
            h0[i]  = sigf(go0.y) * tanhfast(cn);
        }
        {
            float cn = sigf(if1.y) * co1[i] + sigf(if1.x) * tanhfast(go1.x);
            c1v[i] = cn;
            h1v[i] = sigf(go1.y) * tanhfast(cn);
        }
    }
#pragma unroll
    for (int q = 0; q < 2; q++) {
        *reinterpret_cast<float4*>(cstT + (size_t)u0 * NP + nb + 4 * q) =
            make_float4(c0v[4 * q], c0v[4 * q + 1], c0v[4 * q + 2], c0v[4 * q + 3]);
        *reinterpret_cast<float4*>(cstT + (size_t)u1 * NP + nb + 4 * q) =
            make_float4(c1v[4 * q], c1v[4 * q + 1], c1v[4 * q + 2], c1v[4 * q + 3]);
        *reinterpret_cast<float4*>(houtT + (size_t)u0 * NP + nb + 4 * q) =
            make_float4(h0[4 * q], h0[4 * q + 1], h0[4 * q + 2], h0[4 * q + 3]);
        *reinterpret_cast<float4*>(houtT + (size_t)u1 * NP + nb + 4 * q) =
            make_float4(h1v[4 * q], h1v[4 * q + 1], h1v[4 * q + 2], h1v[4 * q + 3]);
    }
}

// ------------------------- linear + ReLU + LayerNorm ------------------------
template <int F, bool RELU_OUT>
__global__ void __launch_bounds__(NTHR, 3)
out_kernel(const float* __restrict__ xin, const float* __restrict__ hfinT,
           const float* __restrict__ LT, const float* __restrict__ lb,
           const float* __restrict__ gma, const float* __restrict__ bta,
           float* __restrict__ out) {
    constexpr int K  = F + LH;
    constexpr int NT = K / KT;
    __shared__ float pool[TM * VST];
    float* sAf = pool;
    float* sBf = pool + KT * AST2;
    float* sV  = pool;
    __shared__ float sMu[TM], sR[TM];

    const int tid  = threadIdx.x;
    const int m0   = blockIdx.x * TM;
    const int nIdx = tid & 15;
    const int mIdx = tid >> 4;

    u64 acc[8][4];
    {
        ulonglong2 b0 = *reinterpret_cast<const ulonglong2*>(lb + nIdx * 4);
        ulonglong2 b1 = *reinterpret_cast<const ulonglong2*>(lb + 64 + nIdx * 4);
        u64 bj[4] = {b0.x, b0.y, b1.x, b1.y};
#pragma unroll
        for (int i = 0; i < 8; i++)
#pragma unroll
            for (int j = 0; j < 4; j++) acc[i][j] = bj[j];
    }

#pragma unroll 1
    for (int kt = 0; kt < NT; kt++) {
        const int k0 = kt * KT;
        __syncthreads();
        if (k0 < F) {
#pragma unroll
            for (int it = 0; it < 4; it++) {
                int idx = tid + it * NTHR;
                int m = idx & 63, kq = idx >> 6;
                int row = m0 + m;
                row = row < N ? row : N - 1;
                float4 v = *reinterpret_cast<const float4*>(xin + (size_t)row * F + k0 + kq * 4);
                float* base = sAf + (size_t)(kq * 4) * AST2 + 2 * m;
                *reinterpret_cast<float2*>(base)            = make_float2(v.x, v.x);
                *reinterpret_cast<float2*>(base + AST2)     = make_float2(v.y, v.y);
                *reinterpret_cast<float2*>(base + 2 * AST2) = make_float2(v.z, v.z);
                *reinterpret_cast<float2*>(base + 3 * AST2) = make_float2(v.w, v.w);
            }
        } else {
#pragma unroll
            for (int it = 0; it < 8; it++) {
                int idx = tid + it * NTHR;
                int kk = idx >> 5, p = idx & 31;
                float2 v = *reinterpret_cast<const float2*>(
                    hfinT + (size_t)(k0 - F + kk) * NP + m0 + 2 * p);
                *reinterpret_cast<float4*>(sAf + (size_t)kk * AST2 + 4 * p) =
                    make_float4(v.x, v.x, v.y, v.y);
            }
        }
#pragma unroll
        for (int it = 0; it < 8; it++) {
            int idx = tid + it * NTHR;
            int kk = idx >> 5, q = idx & 31;
            *reinterpret_cast<float4*>(sBf + (size_t)kk * HID + 4 * q) =
                *reinterpret_cast<const float4*>(LT + (size_t)(k0 + kk) * HID + 4 * q);
        }
        __syncthreads();

#pragma unroll 4
        for (int kk = 0; kk < KT; kk++) {
            const float* ra = sAf + (size_t)kk * AST2 + mIdx * 16;
            const float* rb = sBf + (size_t)kk * HID;
            ulonglong2 a0 = *reinterpret_cast<const ulonglong2*>(ra);
            ulonglong2 a1 = *reinterpret_cast<const ulonglong2*>(ra + 4);
            ulonglong2 a2 = *reinterpret_cast<const ulonglong2*>(ra + 8);
            ulonglong2 a3 = *reinterpret_cast<const ulonglong2*>(ra + 12);
            ulonglong2 b01 = *reinterpret_cast<const ulonglong2*>(rb + nIdx * 4);
            ulonglong2 b23 = *reinterpret_cast<const ulonglong2*>(rb + 64 + nIdx * 4);
            u64 a[8] = {a0.x, a0.y, a1.x, a1.y, a2.x, a2.y, a3.x, a3.y};
            u64 b[4] = {b01.x, b01.y, b23.x, b23.y};
#pragma unroll
            for (int i = 0; i < 8; i++)
#pragma unroll
                for (int j = 0; j < 4; j++) fma2(acc[i][j], a[i], b[j]);
        }
    }
    __syncthreads();

#pragma unroll
    for (int i = 0; i < 8; i++) {
        float* row = sV + (size_t)(mIdx * 8 + i) * VST;
        float2 p0 = unpk(acc[i][0]), p1 = unpk(acc[i][1]);
        float2 p2 = unpk(acc[i][2]), p3 = unpk(acc[i][3]);
        *reinterpret_cast<float4*>(row + nIdx * 4) =
            make_float4(fmaxf(p0.x, 0.f), fmaxf(p0.y, 0.f), fmaxf(p1.x, 0.f), fmaxf(p1.y, 0.f));
        *reinterpret_cast<float4*>(row + 64 + nIdx * 4) =
            make_float4(fmaxf(p2.x, 0.f), fmaxf(p2.y, 0.f), fmaxf(p3.x, 0.f), fmaxf(p3.y, 0.f));
    }
    __syncthreads();

    if (tid < TM) {
        float s = 0.0f, s2 = 0.0f;
        for (int cidx = 0; cidx < HID; cidx++) {
            float v = sV[(size_t)tid * VST + cidx];
            s += v; s2 += v * v;
        }
        float mu  = s * (1.0f / HID);
        float var = s2 * (1.0f / HID) - mu * mu;
        sMu[tid] = mu;
        sR[tid]  = rsqrtf(var + EPS);
    }
    __syncthreads();

    for (int idx = tid; idx < TM * HID; idx += NTHR) {
        int m = idx >> 7, cc = idx & 127;
        int n = m0 + m;
        if (n < N) {
            float v = (sV[(size_t)m * VST + cc] - sMu[m]) * sR[m] * gma[cc] + bta[cc];
            out[(size_t)n * HID + cc] = RELU_OUT ? fmaxf(v, 0.0f) : v;
        }
    }
}

// ------------------------- launch --------------------------------------------
extern "C" void kernel_launch(void* const* d_in, const int* in_sizes, int n_in,
                              void* d_out, int out_size) {
    const float* x    = (const float*)d_in[0];
    const int*   eraw = (const int*)d_in[1];
    const float* W1ih = (const float*)d_in[2];
    const float* W1hh = (const float*)d_in[3];
    const float* b1   = (const float*)d_in[4];
    const float* l1W  = (const float*)d_in[5];
    const float* l1b  = (const float*)d_in[6];
    const float* g1   = (const float*)d_in[7];
    const float* be1  = (const float*)d_in[8];
    const float* W2ih = (const float*)d_in[9];
    const float* W2hh = (const float*)d_in[10];
    const float* b2   = (const float*)d_in[11];
    const float* l2W  = (const float*)d_in[12];
    const float* l2b  = (const float*)d_in[13];
    const float* g2   = (const float*)d_in[14];
    const float* be2  = (const float*)d_in[15];

    float *pBx1, *pBh1, *pBx2, *pBh2, *pbc1, *pbc2, *pL1, *pL2;
    float *phA, *phB, *pc, *ph1;
    cudaGetSymbolAddress((void**)&pBx1, g_Bx1);
    cudaGetSymbolAddress((void**)&pBh1, g_Bh1);
    cudaGetSymbolAddress((void**)&pBx2, g_Bx2);
    cudaGetSymbolAddress((void**)&pBh2, g_Bh2);
    cudaGetSymbolAddress((void**)&pbc1, g_bc1);
    cudaGetSymbolAddress((void**)&pbc2, g_bc2);
    cudaGetSymbolAddress((void**)&pL1, g_L1T);
    cudaGetSymbolAddress((void**)&pL2, g_L2T);
    cudaGetSymbolAddress((void**)&phA, g_hA);
    cudaGetSymbolAddress((void**)&phB, g_hB);
    cudaGetSymbolAddress((void**)&pc, g_cS);
    cudaGetSymbolAddress((void**)&ph1, g_h1);

    cvt_src_kernel<<<(E + 1023) / 1024, 1024>>>(eraw);
    prep_kernel<<<256, 256>>>(W1ih, W1hh, b1, l1W, W2ih, W2hh, b2, l2W);

    const dim3 pgrid(MB, G4 / TC);          // 782 x 4
    const int  s0blocks = (128 * NP) / 256; // 25024

    // ---------------- layer 1 ----------------
    pgemm_kernel<F1><<<pgrid, NTHR>>>(x, pBx1, pbc1);
    step0_kernel<<<s0blocks, 256>>>(phA, pc);
    for (int t = 1; t < DEG; t++) {
        float* hw = (t & 1) ? phB : phA;
        float* hr = (t & 1) ? phA : phB;
        lstm_step_kernel<<<pgrid, NTHR>>>(t, pBh1, hr, hw, pc);
    }
    // t = 7 (odd) -> final h in phB
    out_kernel<F1, true><<<MB, NTHR>>>(x, phB, pL1, l1b, g1, be1, ph1);

    // ---------------- layer 2 ----------------
    pgemm_kernel<HID><<<pgrid, NTHR>>>(ph1, pBx2, pbc2);
    step0_kernel<<<s0blocks, 256>>>(phA, pc);
    for (int t = 1; t < DEG; t++) {
        float* hw = (t & 1) ? phB : phA;
        float* hr = (t & 1) ? phA : phB;
        lstm_step_kernel<<<pgrid, NTHR>>>(t, pBh2, hr, hw, pc);
    }
    out_kernel<HID, false><<<MB, NTHR>>>(ph1, phB, pL2, l2b, g2, be2, (float*)d_out);
}